// round 1
// baseline (speedup 1.0000x reference)
#include <cuda_runtime.h>
#include <math.h>

// ----------------------------- constants -----------------------------------
#define NSEQ   1024
#define DIM    1024
#define NH     16
#define NKH    4
#define NQH    4
#define DH     64
#define CBS    16
#define STRIDE 16
#define SBS    32
#define NSEL   8
#define NCB    64      // NSEQ/STRIDE
#define NFINE  32      // NCB/2
#define SCALE  0.125f

// ----------------------------- scratch -------------------------------------
__device__ float g_qkv [NSEQ * 1536];
__device__ float g_q   [NH  * NSEQ * DH];
__device__ float g_k   [NKH * NSEQ * DH];
__device__ float g_v   [NKH * NSEQ * DH];
__device__ float g_xk  [NKH * NCB * 1024];
__device__ float g_xv  [NKH * NCB * 1024];
__device__ float g_hk  [NKH * NCB * 1024];
__device__ float g_hv  [NKH * NCB * 1024];
__device__ float g_ck  [NKH * NCB * DH];
__device__ float g_cv  [NKH * NCB * DH];
__device__ float g_ckf [NKH * 65 * DH];
__device__ float g_cvf [NKH * 65 * DH];
__device__ float g_imp [NKH * NSEQ * NFINE];
__device__ int   g_idx [NKH * NSEQ * NSEL];
__device__ float g_cout[NH * NSEQ * DH];
__device__ float g_fout[NH * NSEQ * DH];
__device__ float g_gate[NSEQ * 2 * NH];
__device__ float g_y   [NSEQ * NH * DH];

// ----------------------------- SGEMM ----------------------------------------
// C[M,Nc] = act(A[M,K] @ B[K,Nc] + bias). M % 128 == 0, K % 8 == 0 assumed.
// ACT: 0 none, 1 relu, 2 sigmoid
template<int ACT>
__global__ __launch_bounds__(256)
void sgemm(const float* __restrict__ A, const float* __restrict__ B,
           const float* __restrict__ bias, float* __restrict__ C,
           int M, int Nc, int K)
{
    __shared__ float As[8][128];
    __shared__ float Bs[8][128];
    const int tid = threadIdx.x;
    const int m0 = blockIdx.y * 128;
    const int n0 = blockIdx.x * 128;
    const int tx = tid & 15, ty = tid >> 4;

    float acc[8][8];
#pragma unroll
    for (int i = 0; i < 8; i++)
#pragma unroll
        for (int j = 0; j < 8; j++) acc[i][j] = 0.f;

    const int arow = tid >> 1, acol = (tid & 1) * 4;
    const int brow = tid >> 5, bcol = (tid & 31) * 4;
    const float* Aptr = A + (size_t)(m0 + arow) * K + acol;

    for (int k0 = 0; k0 < K; k0 += 8) {
        float4 av = *(const float4*)(Aptr + k0);
        As[acol + 0][arow] = av.x;
        As[acol + 1][arow] = av.y;
        As[acol + 2][arow] = av.z;
        As[acol + 3][arow] = av.w;

        float4 bv = make_float4(0.f, 0.f, 0.f, 0.f);
        int bn = n0 + bcol;
        const float* Brow = B + (size_t)(k0 + brow) * Nc;
        if (bn + 3 < Nc) {
            bv = *(const float4*)(Brow + bn);
        } else {
            if (bn + 0 < Nc) bv.x = Brow[bn + 0];
            if (bn + 1 < Nc) bv.y = Brow[bn + 1];
            if (bn + 2 < Nc) bv.z = Brow[bn + 2];
        }
        *(float4*)&Bs[brow][bcol] = bv;
        __syncthreads();

#pragma unroll
        for (int kk = 0; kk < 8; kk++) {
            float4 a0 = *(const float4*)&As[kk][ty * 8];
            float4 a1 = *(const float4*)&As[kk][ty * 8 + 4];
            float4 b0 = *(const float4*)&Bs[kk][tx * 8];
            float4 b1 = *(const float4*)&Bs[kk][tx * 8 + 4];
            float a[8] = {a0.x, a0.y, a0.z, a0.w, a1.x, a1.y, a1.z, a1.w};
            float b[8] = {b0.x, b0.y, b0.z, b0.w, b1.x, b1.y, b1.z, b1.w};
#pragma unroll
            for (int i = 0; i < 8; i++)
#pragma unroll
                for (int j = 0; j < 8; j++) acc[i][j] += a[i] * b[j];
        }
        __syncthreads();
    }

#pragma unroll
    for (int i = 0; i < 8; i++) {
        int m = m0 + ty * 8 + i;
#pragma unroll
        for (int j = 0; j < 8; j++) {
            int n = n0 + tx * 8 + j;
            if (n < Nc) {
                float val = acc[i][j];
                if (bias) val += bias[n];
                if (ACT == 1) val = fmaxf(val, 0.f);
                if (ACT == 2) val = 1.f / (1.f + __expf(-val));
                C[(size_t)m * Nc + n] = val;
            }
        }
    }
}

// ------------------------- rope + split -------------------------------------
// qkv (NSEQ x 1536) -> q[h][i][d] (roped), k[kh][i][d] (roped), v[kh][i][d]
__global__ void rope_split(const float* __restrict__ qkv,
                           float* __restrict__ q, float* __restrict__ k,
                           float* __restrict__ v)
{
    int id = blockIdx.x * blockDim.x + threadIdx.x;   // NSEQ * 768
    int i  = id / 768;
    int c2 = id % 768;
    int c  = c2 * 2;
    float x1 = qkv[i * 1536 + c];
    float x2 = qkv[i * 1536 + c + 1];
    if (c < 1280) {
        int d  = c & 63;
        int d2 = d >> 1;
        double inv = pow(10000.0, -(double)d2 / 32.0);
        double ang = (double)i * inv;
        float cs = (float)cos(ang);
        float sn = (float)sin(ang);
        float o1 = x1 * cs - x2 * sn;
        float o2 = x2 * cs + x1 * sn;
        if (c < 1024) {
            int h = c >> 6;
            float* dst = q + ((size_t)h * NSEQ + i) * DH + d;
            dst[0] = o1; dst[1] = o2;
        } else {
            int kh = (c - 1024) >> 6;
            float* dst = k + ((size_t)kh * NSEQ + i) * DH + d;
            dst[0] = o1; dst[1] = o2;
        }
    } else {
        int kh = (c - 1280) >> 6;
        int d  = c & 63;
        float* dst = v + ((size_t)kh * NSEQ + i) * DH + d;
        dst[0] = x1; dst[1] = x2;
    }
}

// -------------------- build compressed-MLP inputs ---------------------------
__global__ void build_x(const float* __restrict__ k, const float* __restrict__ v,
                        const float* __restrict__ kpos, const float* __restrict__ vpos,
                        float* __restrict__ xk, float* __restrict__ xv)
{
    int e = blockIdx.x * 256 + threadIdx.x;   // NKH*NCB*1024
    int r = e >> 10;                          // kh*64 + blk
    int c = e & 1023;                         // ci*64 + d
    int kh = r >> 6, blk = r & 63;
    int ci = c >> 6, d = c & 63;
    int src = ((kh * NSEQ) + blk * STRIDE + ci) * DH + d;
    int pos = (kh * CBS + ci) * DH + d;
    xk[e] = k[src] + kpos[pos];
    xv[e] = v[src] + vpos[pos];
}

// ------------------------ assemble ck_full / cv_full ------------------------
__global__ void assemble_c(const float* __restrict__ ck, const float* __restrict__ cv,
                           const float* __restrict__ memkv,
                           float* __restrict__ ckf, float* __restrict__ cvf)
{
    int e = blockIdx.x * 256 + threadIdx.x;   // 4*65*64 = 16640
    int kh  = e / (65 * 64);
    int rem = e % (65 * 64);
    int j = rem / 64, d = rem % 64;
    if (j == 0) {
        ckf[e] = memkv[kh * DH + d];
        cvf[e] = memkv[NKH * DH + kh * DH + d];
    } else {
        int src = (kh * NCB + (j - 1)) * DH + d;
        ckf[e] = ck[src];
        cvf[e] = cv[src];
    }
}

// --------------------------- coarse attention -------------------------------
// grid (32, NKH), block 256 (8 warps). CTA handles 32 queries for one kh.
__global__ __launch_bounds__(256)
void coarse_attn(const float* __restrict__ q, const float* __restrict__ ckf,
                 const float* __restrict__ cvf, float* __restrict__ cout,
                 float* __restrict__ imp)
{
    __shared__ float s_ck[65 * 64];
    __shared__ float s_cv[65 * 64];
    __shared__ float s_imp[32 * 32];
    const int kh = blockIdx.y;
    const int q0 = blockIdx.x * 32;
    const int tid = threadIdx.x;
    for (int e = tid; e < 65 * 64; e += 256) {
        s_ck[e] = ckf[kh * 65 * 64 + e];
        s_cv[e] = cvf[kh * 65 * 64 + e];
    }
    for (int e = tid; e < 32 * 32; e += 256) s_imp[e] = 0.f;
    __syncthreads();

    const int warp = tid >> 5, lane = tid & 31;
    for (int unit = warp; unit < 128; unit += 8) {
        const int ql = unit >> 2;
        const int qh = unit & 3;
        const int qi = q0 + ql;
        const int h  = kh * NQH + qh;
        const float* qp = q + ((size_t)h * NSEQ + qi) * DH;
        const float qa = qp[lane], qb = qp[lane + 32];

        float s0 = 0.f, s1 = 0.f, s2 = -INFINITY;
        for (int j = 0; j < 65; j++) {
            float part = qa * s_ck[j * 64 + lane] + qb * s_ck[j * 64 + lane + 32];
#pragma unroll
            for (int off = 16; off; off >>= 1)
                part += __shfl_xor_sync(0xffffffffu, part, off);
            float sj = part * SCALE;
            if (j == lane)                s0 = sj;
            if (j == lane + 32)           s1 = sj;
            if (j == 64 && lane == 0)     s2 = sj;
        }
        // importance: scaled logits excluding mem slot (j>=1)
        if (lane >= 1) atomicAdd(&s_imp[ql * 32 + ((lane - 1) >> 1)], s0);
        atomicAdd(&s_imp[ql * 32 + ((lane + 31) >> 1)], s1);
        if (lane == 0) atomicAdd(&s_imp[ql * 32 + 31], s2);

        // softmax over 65
        float m = fmaxf(s0, s1);
        if (lane == 0) m = fmaxf(m, s2);
#pragma unroll
        for (int off = 16; off; off >>= 1)
            m = fmaxf(m, __shfl_xor_sync(0xffffffffu, m, off));
        float e0 = __expf(s0 - m);
        float e1 = __expf(s1 - m);
        float e2 = (lane == 0) ? __expf(s2 - m) : 0.f;
        float den = e0 + e1 + e2;
#pragma unroll
        for (int off = 16; off; off >>= 1)
            den += __shfl_xor_sync(0xffffffffu, den, off);

        float o0 = 0.f, o1 = 0.f;
        for (int j = 0; j < 65; j++) {
            float src = (j < 32) ? e0 : ((j < 64) ? e1 : e2);
            float p = __shfl_sync(0xffffffffu, src, j & 31);
            o0 += p * s_cv[j * 64 + lane];
            o1 += p * s_cv[j * 64 + lane + 32];
        }
        float invd = 1.f / den;
        float* op = cout + ((size_t)h * NSEQ + qi) * DH;
        op[lane]      = o0 * invd;
        op[lane + 32] = o1 * invd;
    }
    __syncthreads();
    for (int e = tid; e < 32 * 32; e += 256) {
        int ql = e >> 5, f = e & 31;
        imp[((size_t)kh * NSEQ + q0 + ql) * NFINE + f] = s_imp[e] * 0.125f; // /(QH*npf)
    }
}

// ------------------------------ top-k ---------------------------------------
// grid NSEQ, block 128: warp w = kh
__global__ void topk_kernel(const float* __restrict__ imp, int* __restrict__ idx)
{
    const int i = blockIdx.x;
    const int kh = threadIdx.x >> 5;
    const int lane = threadIdx.x & 31;
    float v = imp[((size_t)kh * NSEQ + i) * NFINE + lane];
    for (int s = 0; s < NSEL; s++) {
        float bv = v; int bi = lane;
#pragma unroll
        for (int off = 16; off; off >>= 1) {
            float ov = __shfl_xor_sync(0xffffffffu, bv, off);
            int   oi = __shfl_xor_sync(0xffffffffu, bi, off);
            if (ov > bv || (ov == bv && oi < bi)) { bv = ov; bi = oi; }
        }
        if (lane == 0) idx[((size_t)kh * NSEQ + i) * NSEL + s] = bi;
        if (lane == bi) v = -INFINITY;
    }
}

// --------------------------- fine attention ---------------------------------
// grid (NSEQ, NKH), block 128 (warp = q-head)
__global__ __launch_bounds__(128)
void fine_attn(const float* __restrict__ q, const float* __restrict__ k,
               const float* __restrict__ v, const int* __restrict__ idx,
               float* __restrict__ fout)
{
    __shared__ float ks[128 * 65];     // padded stride 65 (bank-conflict free)
    __shared__ float qs[4 * 64];
    __shared__ float ssim[4 * 256];
    __shared__ int   sidx[8];
    const int i = blockIdx.x, kh = blockIdx.y;
    const int tid = threadIdx.x, warp = tid >> 5, lane = tid & 31;

    if (tid < 8) sidx[tid] = idx[((size_t)kh * NSEQ + i) * NSEL + tid];
    for (int t = tid; t < 256; t += 128) {
        int h = t >> 6, d = t & 63;
        qs[t] = q[((size_t)(kh * NQH + h) * NSEQ + i) * DH + d];
    }
    __syncthreads();

    // Phase A: logits (two chunks of 4 blocks = 128 keys each)
    for (int c = 0; c < 2; c++) {
        for (int e = tid; e < 2048; e += 128) {
            int r = e >> 4, d4 = e & 15;
            int blk = sidx[c * 4 + (r >> 5)];
            float4 kv = *(const float4*)&k[(((size_t)kh * NSEQ) + blk * SBS + (r & 31)) * DH + d4 * 4];
            float* dst = &ks[r * 65 + d4 * 4];
            dst[0] = kv.x; dst[1] = kv.y; dst[2] = kv.z; dst[3] = kv.w;
        }
        __syncthreads();
        float a0 = 0.f, a1 = 0.f, a2 = 0.f, a3 = 0.f;
#pragma unroll
        for (int d = 0; d < 64; d++) {
            float qd = qs[(warp << 6) + d];
            a0 += qd * ks[(lane)      * 65 + d];
            a1 += qd * ks[(lane + 32) * 65 + d];
            a2 += qd * ks[(lane + 64) * 65 + d];
            a3 += qd * ks[(lane + 96) * 65 + d];
        }
        float* sp = &ssim[warp * 256 + c * 128];
        sp[lane]      = a0 * SCALE;
        sp[lane + 32] = a1 * SCALE;
        sp[lane + 64] = a2 * SCALE;
        sp[lane + 96] = a3 * SCALE;
        __syncthreads();
    }

    // Phase B: softmax over 256 (per warp, warp-private ssim slice)
    float m = -INFINITY;
    for (int t = lane; t < 256; t += 32) m = fmaxf(m, ssim[warp * 256 + t]);
#pragma unroll
    for (int off = 16; off; off >>= 1)
        m = fmaxf(m, __shfl_xor_sync(0xffffffffu, m, off));
    float s = 0.f;
    for (int t = lane; t < 256; t += 32) {
        float e = __expf(ssim[warp * 256 + t] - m);
        ssim[warp * 256 + t] = e;
        s += e;
    }
#pragma unroll
    for (int off = 16; off; off >>= 1)
        s += __shfl_xor_sync(0xffffffffu, s, off);

    // preload probabilities into registers (broadcast later via shfl)
    float pr[8];
#pragma unroll
    for (int t = 0; t < 8; t++) pr[t] = ssim[warp * 256 + t * 32 + lane];

    // Phase C: output accumulation over V (reuse ks buffer)
    float o0 = 0.f, o1 = 0.f;
#pragma unroll
    for (int c = 0; c < 2; c++) {
        __syncthreads();
        for (int e = tid; e < 2048; e += 128) {
            int r = e >> 4, d4 = e & 15;
            int blk = sidx[c * 4 + (r >> 5)];
            float4 vv = *(const float4*)&v[(((size_t)kh * NSEQ) + blk * SBS + (r & 31)) * DH + d4 * 4];
            float* dst = &ks[r * 65 + d4 * 4];
            dst[0] = vv.x; dst[1] = vv.y; dst[2] = vv.z; dst[3] = vv.w;
        }
        __syncthreads();
#pragma unroll
        for (int t = 0; t < 4; t++) {
            float pv = pr[c * 4 + t];
#pragma unroll
            for (int j2 = 0; j2 < 32; j2++) {
                float p = __shfl_sync(0xffffffffu, pv, j2);
                int j = t * 32 + j2;
                o0 += p * ks[j * 65 + lane];
                o1 += p * ks[j * 65 + lane + 32];
            }
        }
    }
    float invd = 1.f / s;
    float* op = fout + ((size_t)(kh * NQH + warp) * NSEQ + i) * DH;
    op[lane]      = o0 * invd;
    op[lane + 32] = o1 * invd;
}

// ------------------------------ combine -------------------------------------
__global__ void combine(const float* __restrict__ cout, const float* __restrict__ fout,
                        const float* __restrict__ gates, float* __restrict__ y)
{
    int e = blockIdx.x * 256 + threadIdx.x;   // NSEQ*1024
    int i = e >> 10;
    int c = e & 1023;
    int h = c >> 6, d = c & 63;
    float g0 = gates[i * 32 + 2 * h];
    float g1 = gates[i * 32 + 2 * h + 1];
    int src = ((size_t)h * NSEQ + i) * DH + d;
    y[e] = g0 * cout[src] + g1 * fout[src];
}

// ----------------------------- launcher -------------------------------------
extern "C" void kernel_launch(void* const* d_in, const int* in_sizes, int n_in,
                              void* d_out, int out_size)
{
    const float* inp    = (const float*)d_in[0];
    const float* w_qkv  = (const float*)d_in[1];
    const float* k_pos  = (const float*)d_in[2];
    const float* v_pos  = (const float*)d_in[3];
    const float* mem_kv = (const float*)d_in[4];
    const float* kc_w1  = (const float*)d_in[5];
    const float* kc_b1  = (const float*)d_in[6];
    const float* kc_w2  = (const float*)d_in[7];
    const float* kc_b2  = (const float*)d_in[8];
    const float* vc_w1  = (const float*)d_in[9];
    const float* vc_b1  = (const float*)d_in[10];
    const float* vc_w2  = (const float*)d_in[11];
    const float* vc_b2  = (const float*)d_in[12];
    const float* gate_w = (const float*)d_in[13];
    const float* gate_b = (const float*)d_in[14];
    const float* out_w  = (const float*)d_in[15];
    float* out = (float*)d_out;

    float *p_qkv, *p_q, *p_k, *p_v, *p_xk, *p_xv, *p_hk, *p_hv, *p_ck, *p_cv;
    float *p_ckf, *p_cvf, *p_imp, *p_cout, *p_fout, *p_gate, *p_y;
    int* p_idx;
    cudaGetSymbolAddress((void**)&p_qkv,  g_qkv);
    cudaGetSymbolAddress((void**)&p_q,    g_q);
    cudaGetSymbolAddress((void**)&p_k,    g_k);
    cudaGetSymbolAddress((void**)&p_v,    g_v);
    cudaGetSymbolAddress((void**)&p_xk,   g_xk);
    cudaGetSymbolAddress((void**)&p_xv,   g_xv);
    cudaGetSymbolAddress((void**)&p_hk,   g_hk);
    cudaGetSymbolAddress((void**)&p_hv,   g_hv);
    cudaGetSymbolAddress((void**)&p_ck,   g_ck);
    cudaGetSymbolAddress((void**)&p_cv,   g_cv);
    cudaGetSymbolAddress((void**)&p_ckf,  g_ckf);
    cudaGetSymbolAddress((void**)&p_cvf,  g_cvf);
    cudaGetSymbolAddress((void**)&p_imp,  g_imp);
    cudaGetSymbolAddress((void**)&p_idx,  g_idx);
    cudaGetSymbolAddress((void**)&p_cout, g_cout);
    cudaGetSymbolAddress((void**)&p_fout, g_fout);
    cudaGetSymbolAddress((void**)&p_gate, g_gate);
    cudaGetSymbolAddress((void**)&p_y,    g_y);

    // 1) qkv projection
    sgemm<0><<<dim3(12, 8), 256>>>(inp, w_qkv, nullptr, p_qkv, 1024, 1536, 1024);
    // 2) rope + split
    rope_split<<<3072, 256>>>(p_qkv, p_q, p_k, p_v);
    // 3) compressed-MLP inputs
    build_x<<<1024, 256>>>(p_k, p_v, k_pos, v_pos, p_xk, p_xv);
    // 4) MLP layer 1 (relu)
    sgemm<1><<<dim3(8, 2), 256>>>(p_xk, kc_w1, kc_b1, p_hk, 256, 1024, 1024);
    sgemm<1><<<dim3(8, 2), 256>>>(p_xv, vc_w1, vc_b1, p_hv, 256, 1024, 1024);
    // 5) MLP layer 2
    sgemm<0><<<dim3(1, 2), 256>>>(p_hk, kc_w2, kc_b2, p_ck, 256, 64, 1024);
    sgemm<0><<<dim3(1, 2), 256>>>(p_hv, vc_w2, vc_b2, p_cv, 256, 64, 1024);
    // 6) prepend mem slots
    assemble_c<<<65, 256>>>(p_ck, p_cv, mem_kv, p_ckf, p_cvf);
    // 7) coarse attention + importance
    coarse_attn<<<dim3(32, 4), 256>>>(p_q, p_ckf, p_cvf, p_cout, p_imp);
    // 8) top-8 fine blocks per (kh, query)
    topk_kernel<<<1024, 128>>>(p_imp, p_idx);
    // 9) fine attention
    fine_attn<<<dim3(1024, 4), 128>>>(p_q, p_k, p_v, p_idx, p_fout);
    // 10) gates
    sgemm<2><<<dim3(1, 8), 256>>>(inp, gate_w, gate_b, p_gate, 1024, 32, 1024);
    // 11) gated merge
    combine<<<4096, 256>>>(p_cout, p_fout, p_gate, p_y);
    // 12) output projection
    sgemm<0><<<dim3(8, 8), 256>>>(p_y, out_w, nullptr, out, 1024, 1024, 1024);
}

// round 3
// speedup vs baseline: 2.5317x; 2.5317x over previous
#include <cuda_runtime.h>
#include <math.h>

// ----------------------------- constants -----------------------------------
#define NSEQ   1024
#define DIM    1024
#define NH     16
#define NKH    4
#define NQH    4
#define DH     64
#define CBS    16
#define STRIDE 16
#define SBS    32
#define NSEL   8
#define NCB    64      // NSEQ/STRIDE
#define NFINE  32      // NCB/2
#define SCALE  0.125f

// ----------------------------- scratch -------------------------------------
__device__ float g_qkv [NSEQ * 1536];
__device__ float g_q   [NH  * NSEQ * DH];
__device__ float g_k   [NKH * NSEQ * DH];
__device__ float g_v   [NKH * NSEQ * DH];
__device__ float g_x   [2 * NKH * NCB * 1024];   // [k; v] MLP inputs
__device__ float g_h   [2 * NKH * NCB * 1024];   // hidden
__device__ float g_c   [2 * NKH * NCB * DH];     // ck ; cv
__device__ float g_ckf [NKH * 65 * DH];
__device__ float g_cvf [NKH * 65 * DH];
__device__ float g_imp [NKH * NSEQ * NFINE];
__device__ int   g_idx [NKH * NSEQ * NSEL];
__device__ float g_cout[NH * NSEQ * DH];
__device__ float g_fout[NH * NSEQ * DH];
__device__ float g_gate[NSEQ * 2 * NH];
__device__ float g_y   [NSEQ * NH * DH];
__device__ float g_ct  [NSEQ * 32];
__device__ float g_st  [NSEQ * 32];

// ---------------------- double-buffered SGEMM (BN=128) ----------------------
// C[M,Nc] = act(A @ B + bias).  BM in {64,128}, BN fixed 128, KB=8.
// threads = 2*BM.  Requires Nc % 128 == 0, M % BM == 0, K % 8 == 0.
// Batched over blockIdx.z (selects B/bias pointer pair + A/C strides).
// ACT: 0 none, 1 relu, 2 sigmoid
template<int BM, int ACT>
__global__ __launch_bounds__(BM * 2)
void sgemm_db(const float* __restrict__ A,
              const float* __restrict__ B0, const float* __restrict__ B1,
              const float* __restrict__ bias0, const float* __restrict__ bias1,
              float* __restrict__ C, int Nc, int K, int bsA, int bsC)
{
    constexpr int THREADS = BM * 2;
    constexpr int BPT4 = 256 / THREADS;      // float4 B-loads per thread
    __shared__ float As[2][8][BM];
    __shared__ float Bs[2][8][128];

    const int z = blockIdx.z;
    const float* Bp   = z ? B1 : B0;
    const float* bias = z ? bias1 : bias0;
    A += (size_t)z * bsA;
    C += (size_t)z * bsC;

    const int tid = threadIdx.x;
    const int m0 = blockIdx.y * BM;
    const int n0 = blockIdx.x * 128;
    const int tx = tid & 15, ty = tid >> 4;
    const int arow = tid >> 1, acol = (tid & 1) * 4;
    const float* Aptr = A + (size_t)(m0 + arow) * K + acol;

    int brow[BPT4], bcol[BPT4];
#pragma unroll
    for (int j = 0; j < BPT4; j++) {
        int l = j * THREADS + tid;
        brow[j] = l >> 5;
        bcol[j] = (l & 31) * 4;
    }

    float acc[8][8];
#pragma unroll
    for (int i = 0; i < 8; i++)
#pragma unroll
        for (int j = 0; j < 8; j++) acc[i][j] = 0.f;

    float4 av;
    float4 bv[BPT4];

    // prologue: load k-slab 0 into buffer 0
    av = *(const float4*)(Aptr);
#pragma unroll
    for (int j = 0; j < BPT4; j++)
        bv[j] = *(const float4*)(Bp + (size_t)brow[j] * Nc + n0 + bcol[j]);
    As[0][acol + 0][arow] = av.x;
    As[0][acol + 1][arow] = av.y;
    As[0][acol + 2][arow] = av.z;
    As[0][acol + 3][arow] = av.w;
#pragma unroll
    for (int j = 0; j < BPT4; j++)
        *(float4*)&Bs[0][brow[j]][bcol[j]] = bv[j];
    __syncthreads();

    int cur = 0;
    for (int k0 = 0; k0 < K; k0 += 8) {
        const bool nxt = (k0 + 8) < K;
        if (nxt) {
            av = *(const float4*)(Aptr + k0 + 8);
#pragma unroll
            for (int j = 0; j < BPT4; j++)
                bv[j] = *(const float4*)(Bp + (size_t)(k0 + 8 + brow[j]) * Nc + n0 + bcol[j]);
        }
#pragma unroll
        for (int kk = 0; kk < 8; kk++) {
            float4 a0 = *(const float4*)&As[cur][kk][ty * 8];
            float4 a1 = *(const float4*)&As[cur][kk][ty * 8 + 4];
            float4 b0 = *(const float4*)&Bs[cur][kk][tx * 8];
            float4 b1 = *(const float4*)&Bs[cur][kk][tx * 8 + 4];
            float a[8] = {a0.x, a0.y, a0.z, a0.w, a1.x, a1.y, a1.z, a1.w};
            float b[8] = {b0.x, b0.y, b0.z, b0.w, b1.x, b1.y, b1.z, b1.w};
#pragma unroll
            for (int i = 0; i < 8; i++)
#pragma unroll
                for (int j = 0; j < 8; j++) acc[i][j] += a[i] * b[j];
        }
        if (nxt) {
            int nb = cur ^ 1;
            As[nb][acol + 0][arow] = av.x;
            As[nb][acol + 1][arow] = av.y;
            As[nb][acol + 2][arow] = av.z;
            As[nb][acol + 3][arow] = av.w;
#pragma unroll
            for (int j = 0; j < BPT4; j++)
                *(float4*)&Bs[nb][brow[j]][bcol[j]] = bv[j];
        }
        __syncthreads();
        cur ^= 1;
    }

    // epilogue
#pragma unroll
    for (int i = 0; i < 8; i++) {
        int m = m0 + ty * 8 + i;
        float* crow = C + (size_t)m * Nc + n0 + tx * 8;
        float vals[8];
#pragma unroll
        for (int j = 0; j < 8; j++) {
            float v = acc[i][j];
            if (bias) v += bias[n0 + tx * 8 + j];
            if (ACT == 1) v = fmaxf(v, 0.f);
            if (ACT == 2) v = 1.f / (1.f + __expf(-v));
            vals[j] = v;
        }
        *(float4*)(crow)     = make_float4(vals[0], vals[1], vals[2], vals[3]);
        *(float4*)(crow + 4) = make_float4(vals[4], vals[5], vals[6], vals[7]);
    }
}

// ------------------------- skinny GEMM (N<=64) ------------------------------
// C[M,NC] = act(A[M,K] @ B[K,NC] + bias). 16 rows per CTA, 256 threads.
// Batched over blockIdx.y.
template<int NC, int ACT>
__global__ __launch_bounds__(256)
void skinny_gemm(const float* __restrict__ A,
                 const float* __restrict__ B0, const float* __restrict__ B1,
                 const float* __restrict__ bias0, const float* __restrict__ bias1,
                 float* __restrict__ C, int K, int bsA, int bsC)
{
    constexpr int G   = 256 / NC;   // row groups
    constexpr int RPT = 16 / G;     // rows per thread
    __shared__ float As[16][68];    // stride 68: float4-aligned rows
    __shared__ float Bs[64][NC];

    const int z = blockIdx.y;
    const float* Bp   = z ? B1 : B0;
    const float* bias = z ? bias1 : bias0;
    A += (size_t)z * bsA;
    C += (size_t)z * bsC;

    const int tid = threadIdx.x;
    const int r0 = blockIdx.x * 16;
    const int col = tid % NC;
    const int rgrp = tid / NC;

    float acc[RPT];
#pragma unroll
    for (int r = 0; r < RPT; r++) acc[r] = 0.f;

    const int arow = tid >> 4, acol = (tid & 15) * 4;
    constexpr int F4R = NC / 4;          // float4 per B row
    constexpr int BLT = NC / 16;         // B float4 loads per thread

    for (int k0 = 0; k0 < K; k0 += 64) {
        float4 a4 = *(const float4*)(A + (size_t)(r0 + arow) * K + k0 + acol);
        *(float4*)&As[arow][acol] = a4;
#pragma unroll
        for (int t = 0; t < BLT; t++) {
            int l = t * 256 + tid;
            int row = l / F4R, c4 = (l % F4R) * 4;
            float4 b4 = *(const float4*)(Bp + (size_t)(k0 + row) * NC + c4);
            *(float4*)&Bs[row][c4] = b4;
        }
        __syncthreads();
#pragma unroll 8
        for (int kk = 0; kk < 64; kk++) {
            float b = Bs[kk][col];
#pragma unroll
            for (int r = 0; r < RPT; r++)
                acc[r] += As[rgrp * RPT + r][kk] * b;
        }
        __syncthreads();
    }

#pragma unroll
    for (int r = 0; r < RPT; r++) {
        float v = acc[r];
        if (bias) v += bias[col];
        if (ACT == 1) v = fmaxf(v, 0.f);
        if (ACT == 2) v = 1.f / (1.f + __expf(-v));
        C[(size_t)(r0 + rgrp * RPT + r) * NC + col] = v;
    }
}

// ------------------------- rope table + rope/split --------------------------
__global__ void rope_table(float* __restrict__ ct, float* __restrict__ st)
{
    int id = blockIdx.x * 256 + threadIdx.x;   // 32768
    int i = id >> 5, d2 = id & 31;
    double inv = pow(10000.0, -(double)d2 / 32.0);
    double ang = (double)i * inv;
    ct[id] = (float)cos(ang);
    st[id] = (float)sin(ang);
}

__global__ void rope_split(const float* __restrict__ qkv,
                           const float* __restrict__ ct, const float* __restrict__ st,
                           float* __restrict__ q, float* __restrict__ k,
                           float* __restrict__ v)
{
    int id = blockIdx.x * blockDim.x + threadIdx.x;   // NSEQ * 768
    int i  = id / 768;
    int c2 = id % 768;
    int c  = c2 * 2;
    float x1 = qkv[i * 1536 + c];
    float x2 = qkv[i * 1536 + c + 1];
    if (c < 1280) {
        int d  = c & 63;
        int d2 = d >> 1;
        float cs = ct[i * 32 + d2];
        float sn = st[i * 32 + d2];
        float o1 = x1 * cs - x2 * sn;
        float o2 = x2 * cs + x1 * sn;
        if (c < 1024) {
            int h = c >> 6;
            float* dst = q + ((size_t)h * NSEQ + i) * DH + d;
            dst[0] = o1; dst[1] = o2;
        } else {
            int kh = (c - 1024) >> 6;
            float* dst = k + ((size_t)kh * NSEQ + i) * DH + d;
            dst[0] = o1; dst[1] = o2;
        }
    } else {
        int kh = (c - 1280) >> 6;
        int d  = c & 63;
        float* dst = v + ((size_t)kh * NSEQ + i) * DH + d;
        dst[0] = x1; dst[1] = x2;
    }
}

// -------------------- build compressed-MLP inputs ---------------------------
__global__ void build_x(const float* __restrict__ k, const float* __restrict__ v,
                        const float* __restrict__ kpos, const float* __restrict__ vpos,
                        float* __restrict__ x)
{
    int e = blockIdx.x * 256 + threadIdx.x;   // NKH*NCB*1024
    int r = e >> 10;
    int c = e & 1023;
    int kh = r >> 6, blk = r & 63;
    int ci = c >> 6, d = c & 63;
    int src = ((kh * NSEQ) + blk * STRIDE + ci) * DH + d;
    int pos = (kh * CBS + ci) * DH + d;
    x[e]               = k[src] + kpos[pos];
    x[e + 262144]      = v[src] + vpos[pos];
}

// ------------------------ assemble ck_full / cv_full ------------------------
__global__ void assemble_c(const float* __restrict__ c, const float* __restrict__ memkv,
                           float* __restrict__ ckf, float* __restrict__ cvf)
{
    int e = blockIdx.x * 256 + threadIdx.x;   // 4*65*64 = 16640
    int kh  = e / (65 * 64);
    int rem = e % (65 * 64);
    int j = rem / 64, d = rem % 64;
    if (j == 0) {
        ckf[e] = memkv[kh * DH + d];
        cvf[e] = memkv[NKH * DH + kh * DH + d];
    } else {
        int src = (kh * NCB + (j - 1)) * DH + d;
        ckf[e] = c[src];
        cvf[e] = c[src + NKH * NCB * DH];
    }
}

// --------------------------- coarse attention -------------------------------
__global__ __launch_bounds__(256)
void coarse_attn(const float* __restrict__ q, const float* __restrict__ ckf,
                 const float* __restrict__ cvf, float* __restrict__ cout,
                 float* __restrict__ imp)
{
    __shared__ float s_ck[65 * 64];
    __shared__ float s_cv[65 * 64];
    __shared__ float s_imp[32 * 32];
    const int kh = blockIdx.y;
    const int q0 = blockIdx.x * 32;
    const int tid = threadIdx.x;
    for (int e = tid; e < 65 * 64; e += 256) {
        s_ck[e] = ckf[kh * 65 * 64 + e];
        s_cv[e] = cvf[kh * 65 * 64 + e];
    }
    for (int e = tid; e < 32 * 32; e += 256) s_imp[e] = 0.f;
    __syncthreads();

    const int warp = tid >> 5, lane = tid & 31;
    for (int unit = warp; unit < 128; unit += 8) {
        const int ql = unit >> 2;
        const int qh = unit & 3;
        const int qi = q0 + ql;
        const int h  = kh * NQH + qh;
        const float* qp = q + ((size_t)h * NSEQ + qi) * DH;
        const float qa = qp[lane], qb = qp[lane + 32];

        float s0 = 0.f, s1 = 0.f, s2 = -INFINITY;
        for (int j = 0; j < 65; j++) {
            float part = qa * s_ck[j * 64 + lane] + qb * s_ck[j * 64 + lane + 32];
#pragma unroll
            for (int off = 16; off; off >>= 1)
                part += __shfl_xor_sync(0xffffffffu, part, off);
            float sj = part * SCALE;
            if (j == lane)                s0 = sj;
            if (j == lane + 32)           s1 = sj;
            if (j == 64 && lane == 0)     s2 = sj;
        }
        if (lane >= 1) atomicAdd(&s_imp[ql * 32 + ((lane - 1) >> 1)], s0);
        atomicAdd(&s_imp[ql * 32 + ((lane + 31) >> 1)], s1);
        if (lane == 0) atomicAdd(&s_imp[ql * 32 + 31], s2);

        float m = fmaxf(s0, s1);
        if (lane == 0) m = fmaxf(m, s2);
#pragma unroll
        for (int off = 16; off; off >>= 1)
            m = fmaxf(m, __shfl_xor_sync(0xffffffffu, m, off));
        float e0 = __expf(s0 - m);
        float e1 = __expf(s1 - m);
        float e2 = (lane == 0) ? __expf(s2 - m) : 0.f;
        float den = e0 + e1 + e2;
#pragma unroll
        for (int off = 16; off; off >>= 1)
            den += __shfl_xor_sync(0xffffffffu, den, off);

        float o0 = 0.f, o1 = 0.f;
        for (int j = 0; j < 65; j++) {
            float src = (j < 32) ? e0 : ((j < 64) ? e1 : e2);
            float p = __shfl_sync(0xffffffffu, src, j & 31);
            o0 += p * s_cv[j * 64 + lane];
            o1 += p * s_cv[j * 64 + lane + 32];
        }
        float invd = 1.f / den;
        float* op = cout + ((size_t)h * NSEQ + qi) * DH;
        op[lane]      = o0 * invd;
        op[lane + 32] = o1 * invd;
    }
    __syncthreads();
    for (int e = tid; e < 32 * 32; e += 256) {
        int ql = e >> 5, f = e & 31;
        imp[((size_t)kh * NSEQ + q0 + ql) * NFINE + f] = s_imp[e] * 0.125f;
    }
}

// ------------------------------ top-k ---------------------------------------
__global__ void topk_kernel(const float* __restrict__ imp, int* __restrict__ idx)
{
    const int i = blockIdx.x;
    const int kh = threadIdx.x >> 5;
    const int lane = threadIdx.x & 31;
    float v = imp[((size_t)kh * NSEQ + i) * NFINE + lane];
    for (int s = 0; s < NSEL; s++) {
        float bv = v; int bi = lane;
#pragma unroll
        for (int off = 16; off; off >>= 1) {
            float ov = __shfl_xor_sync(0xffffffffu, bv, off);
            int   oi = __shfl_xor_sync(0xffffffffu, bi, off);
            if (ov > bv || (ov == bv && oi < bi)) { bv = ov; bi = oi; }
        }
        if (lane == 0) idx[((size_t)kh * NSEQ + i) * NSEL + s] = bi;
        if (lane == bi) v = -INFINITY;
    }
}

// --------------------------- fine attention ---------------------------------
__global__ __launch_bounds__(128)
void fine_attn(const float* __restrict__ q, const float* __restrict__ k,
               const float* __restrict__ v, const int* __restrict__ idx,
               float* __restrict__ fout)
{
    __shared__ float ks[128 * 65];
    __shared__ float qs[4 * 64];
    __shared__ float ssim[4 * 256];
    __shared__ int   sidx[8];
    const int i = blockIdx.x, kh = blockIdx.y;
    const int tid = threadIdx.x, warp = tid >> 5, lane = tid & 31;

    if (tid < 8) sidx[tid] = idx[((size_t)kh * NSEQ + i) * NSEL + tid];
    for (int t = tid; t < 256; t += 128) {
        int h = t >> 6, d = t & 63;
        qs[t] = q[((size_t)(kh * NQH + h) * NSEQ + i) * DH + d];
    }
    __syncthreads();

    for (int c = 0; c < 2; c++) {
        for (int e = tid; e < 2048; e += 128) {
            int r = e >> 4, d4 = e & 15;
            int blk = sidx[c * 4 + (r >> 5)];
            float4 kv = *(const float4*)&k[(((size_t)kh * NSEQ) + blk * SBS + (r & 31)) * DH + d4 * 4];
            float* dst = &ks[r * 65 + d4 * 4];
            dst[0] = kv.x; dst[1] = kv.y; dst[2] = kv.z; dst[3] = kv.w;
        }
        __syncthreads();
        float a0 = 0.f, a1 = 0.f, a2 = 0.f, a3 = 0.f;
#pragma unroll
        for (int d = 0; d < 64; d++) {
            float qd = qs[(warp << 6) + d];
            a0 += qd * ks[(lane)      * 65 + d];
            a1 += qd * ks[(lane + 32) * 65 + d];
            a2 += qd * ks[(lane + 64) * 65 + d];
            a3 += qd * ks[(lane + 96) * 65 + d];
        }
        float* sp = &ssim[warp * 256 + c * 128];
        sp[lane]      = a0 * SCALE;
        sp[lane + 32] = a1 * SCALE;
        sp[lane + 64] = a2 * SCALE;
        sp[lane + 96] = a3 * SCALE;
        __syncthreads();
    }

    float m = -INFINITY;
    for (int t = lane; t < 256; t += 32) m = fmaxf(m, ssim[warp * 256 + t]);
#pragma unroll
    for (int off = 16; off; off >>= 1)
        m = fmaxf(m, __shfl_xor_sync(0xffffffffu, m, off));
    float s = 0.f;
    for (int t = lane; t < 256; t += 32) {
        float e = __expf(ssim[warp * 256 + t] - m);
        ssim[warp * 256 + t] = e;
        s += e;
    }
#pragma unroll
    for (int off = 16; off; off >>= 1)
        s += __shfl_xor_sync(0xffffffffu, s, off);

    float pr[8];
#pragma unroll
    for (int t = 0; t < 8; t++) pr[t] = ssim[warp * 256 + t * 32 + lane];

    float o0 = 0.f, o1 = 0.f;
#pragma unroll
    for (int c = 0; c < 2; c++) {
        __syncthreads();
        for (int e = tid; e < 2048; e += 128) {
            int r = e >> 4, d4 = e & 15;
            int blk = sidx[c * 4 + (r >> 5)];
            float4 vv = *(const float4*)&v[(((size_t)kh * NSEQ) + blk * SBS + (r & 31)) * DH + d4 * 4];
            float* dst = &ks[r * 65 + d4 * 4];
            dst[0] = vv.x; dst[1] = vv.y; dst[2] = vv.z; dst[3] = vv.w;
        }
        __syncthreads();
#pragma unroll
        for (int t = 0; t < 4; t++) {
            float pv = pr[c * 4 + t];
#pragma unroll
            for (int j2 = 0; j2 < 32; j2++) {
                float p = __shfl_sync(0xffffffffu, pv, j2);
                int j = t * 32 + j2;
                o0 += p * ks[j * 65 + lane];
                o1 += p * ks[j * 65 + lane + 32];
            }
        }
    }
    float invd = 1.f / s;
    float* op = fout + ((size_t)(kh * NQH + warp) * NSEQ + i) * DH;
    op[lane]      = o0 * invd;
    op[lane + 32] = o1 * invd;
}

// ------------------------------ combine -------------------------------------
__global__ void combine(const float* __restrict__ cout, const float* __restrict__ fout,
                        const float* __restrict__ gates, float* __restrict__ y)
{
    int e = blockIdx.x * 256 + threadIdx.x;   // NSEQ*1024
    int i = e >> 10;
    int c = e & 1023;
    int h = c >> 6, d = c & 63;
    float g0 = gates[i * 32 + 2 * h];
    float g1 = gates[i * 32 + 2 * h + 1];
    int src = ((size_t)h * NSEQ + i) * DH + d;
    y[e] = g0 * cout[src] + g1 * fout[src];
}

// ----------------------------- launcher -------------------------------------
extern "C" void kernel_launch(void* const* d_in, const int* in_sizes, int n_in,
                              void* d_out, int out_size)
{
    const float* inp    = (const float*)d_in[0];
    const float* w_qkv  = (const float*)d_in[1];
    const float* k_pos  = (const float*)d_in[2];
    const float* v_pos  = (const float*)d_in[3];
    const float* mem_kv = (const float*)d_in[4];
    const float* kc_w1  = (const float*)d_in[5];
    const float* kc_b1  = (const float*)d_in[6];
    const float* kc_w2  = (const float*)d_in[7];
    const float* kc_b2  = (const float*)d_in[8];
    const float* vc_w1  = (const float*)d_in[9];
    const float* vc_b1  = (const float*)d_in[10];
    const float* vc_w2  = (const float*)d_in[11];
    const float* vc_b2  = (const float*)d_in[12];
    const float* gate_w = (const float*)d_in[13];
    const float* gate_b = (const float*)d_in[14];
    const float* out_w  = (const float*)d_in[15];
    float* out = (float*)d_out;

    float *p_qkv, *p_q, *p_k, *p_v, *p_x, *p_h, *p_c;
    float *p_ckf, *p_cvf, *p_imp, *p_cout, *p_fout, *p_gate, *p_y, *p_ct, *p_st;
    int* p_idx;
    cudaGetSymbolAddress((void**)&p_qkv,  g_qkv);
    cudaGetSymbolAddress((void**)&p_q,    g_q);
    cudaGetSymbolAddress((void**)&p_k,    g_k);
    cudaGetSymbolAddress((void**)&p_v,    g_v);
    cudaGetSymbolAddress((void**)&p_x,    g_x);
    cudaGetSymbolAddress((void**)&p_h,    g_h);
    cudaGetSymbolAddress((void**)&p_c,    g_c);
    cudaGetSymbolAddress((void**)&p_ckf,  g_ckf);
    cudaGetSymbolAddress((void**)&p_cvf,  g_cvf);
    cudaGetSymbolAddress((void**)&p_imp,  g_imp);
    cudaGetSymbolAddress((void**)&p_idx,  g_idx);
    cudaGetSymbolAddress((void**)&p_cout, g_cout);
    cudaGetSymbolAddress((void**)&p_fout, g_fout);
    cudaGetSymbolAddress((void**)&p_gate, g_gate);
    cudaGetSymbolAddress((void**)&p_y,    g_y);
    cudaGetSymbolAddress((void**)&p_ct,   g_ct);
    cudaGetSymbolAddress((void**)&p_st,   g_st);

    // 0) rope tables
    rope_table<<<128, 256>>>(p_ct, p_st);
    // 1) qkv projection: [1024,1024] @ [1024,1536]
    sgemm_db<64, 0><<<dim3(12, 16, 1), 128>>>(inp, w_qkv, w_qkv, nullptr, nullptr,
                                              p_qkv, 1536, 1024, 0, 0);
    // 2) rope + split
    rope_split<<<3072, 256>>>(p_qkv, p_ct, p_st, p_q, p_k, p_v);
    // 3) compressed-MLP inputs (k and v halves)
    build_x<<<1024, 256>>>(p_k, p_v, k_pos, v_pos, p_x);
    // 4) MLP layer 1 (relu), batched k/v: [256,1024] @ [1024,1024]
    sgemm_db<64, 1><<<dim3(8, 4, 2), 128>>>(p_x, kc_w1, vc_w1, kc_b1, vc_b1,
                                            p_h, 1024, 1024, 262144, 262144);
    // 5) MLP layer 2, batched k/v: [256,1024] @ [1024,64]
    skinny_gemm<64, 0><<<dim3(16, 2), 256>>>(p_h, kc_w2, vc_w2, kc_b2, vc_b2,
                                             p_c, 1024, 262144, 16384);
    // 6) prepend mem slots
    assemble_c<<<65, 256>>>(p_c, mem_kv, p_ckf, p_cvf);
    // 7) coarse attention + importance
    coarse_attn<<<dim3(32, 4), 256>>>(p_q, p_ckf, p_cvf, p_cout, p_imp);
    // 8) top-8 fine blocks per (kh, query)
    topk_kernel<<<1024, 128>>>(p_imp, p_idx);
    // 9) fine attention
    fine_attn<<<dim3(1024, 4), 128>>>(p_q, p_k, p_v, p_idx, p_fout);
    // 10) gates: [1024,1024] @ [1024,32] + sigmoid
    skinny_gemm<32, 2><<<dim3(64, 1), 256>>>(inp, gate_w, gate_w, gate_b, gate_b,
                                             p_gate, 1024, 0, 0);
    // 11) gated merge
    combine<<<4096, 256>>>(p_cout, p_fout, p_gate, p_y);
    // 12) output projection: [1024,1024] @ [1024,1024]
    sgemm_db<64, 0><<<dim3(8, 16, 1), 128>>>(p_y, out_w, out_w, nullptr, nullptr,
                                             out, 1024, 1024, 0, 0);
}